// round 5
// baseline (speedup 1.0000x reference)
#include <cuda_runtime.h>
#include <cstdint>
#include <math.h>

// Problem: B=8, T_OUT=256, T_IN=512, L=128, D_IN=128, D_ATT=128
// out = concat(x, weighted) (8,256,256) then h (8,128) then c (8,128)
#define OUT_ELEMS (8*256*256)
#define H_OFF (8*256*256)
#define C_OFF (H_OFF + 8*128)

// Scratch (device globals — no allocation allowed)
__device__ float g_xz[8*256*512];     // input projection + bias
__device__ float g_keys[8*512*128];   // attended @ W1 + b1
__device__ float g_q[8*256*128];      // x @ W2 + b2

__device__ __forceinline__ uint32_t smem_u32(const void* p){
  uint32_t a;
  asm("{ .reg .u64 t; cvta.to.shared.u64 t, %1; cvt.u32.u64 %0, t; }" : "=r"(a) : "l"(p));
  return a;
}
__device__ __forceinline__ float tanh_fast(float x){
  float y; asm("tanh.approx.f32 %0, %1;" : "=f"(y) : "f"(x)); return y;
}

// ---------------------------------------------------------------------------
// Generic row-tiled GEMM: C[M,N] = A[M,128] @ B[128,N] + bias[N]
// grid.x = M/16, blockDim.x = N (128 or 512). Thread j owns column j for 16 rows.
// A tile staged transposed in smem; reads are warp-broadcast LDS.128.
// ---------------------------------------------------------------------------
__global__ void gemm16_kernel(const float* __restrict__ A, int lda,
                              const float* __restrict__ Bm,
                              const float* __restrict__ bias,
                              float* __restrict__ C, int ldc, int N)
{
  __shared__ __align__(16) float asT[128*16];
  const int j  = threadIdx.x;
  const int r0 = blockIdx.x * 16;

  for (int idx = j; idx < 2048; idx += blockDim.x){
    int r = idx >> 7, l = idx & 127;
    asT[l*16 + r] = A[(size_t)(r0 + r)*lda + l];
  }
  __syncthreads();

  float bv = bias[j];
  float acc[16];
  #pragma unroll
  for (int r = 0; r < 16; r++) acc[r] = bv;

  #pragma unroll 4
  for (int l = 0; l < 128; l++){
    float wv = Bm[(size_t)l*N + j];
    const float4* ap = (const float4*)&asT[l*16];
    float4 a0 = ap[0], a1 = ap[1], a2 = ap[2], a3 = ap[3];
    acc[0]  = fmaf(a0.x, wv, acc[0]);  acc[1]  = fmaf(a0.y, wv, acc[1]);
    acc[2]  = fmaf(a0.z, wv, acc[2]);  acc[3]  = fmaf(a0.w, wv, acc[3]);
    acc[4]  = fmaf(a1.x, wv, acc[4]);  acc[5]  = fmaf(a1.y, wv, acc[5]);
    acc[6]  = fmaf(a1.z, wv, acc[6]);  acc[7]  = fmaf(a1.w, wv, acc[7]);
    acc[8]  = fmaf(a2.x, wv, acc[8]);  acc[9]  = fmaf(a2.y, wv, acc[9]);
    acc[10] = fmaf(a2.z, wv, acc[10]); acc[11] = fmaf(a2.w, wv, acc[11]);
    acc[12] = fmaf(a3.x, wv, acc[12]); acc[13] = fmaf(a3.y, wv, acc[13]);
    acc[14] = fmaf(a3.z, wv, acc[14]); acc[15] = fmaf(a3.w, wv, acc[15]);
  }

  #pragma unroll
  for (int r = 0; r < 16; r++) C[(size_t)(r0 + r)*ldc + j] = acc[r];
}

// ---------------------------------------------------------------------------
// LSTM scan. Cluster of 2 CTAs per batch element; grid = 16 CTAs total.
// CTA rank r owns state rows m in [64r, 64r+64) — i.e. z columns {g*128 + m}
// for g in {i,f,g,o}. Wr columns for those 256 z-cols are REGISTER-resident:
// thread t handles local col c=t>>1 (256 cols), K-half = t&1, holding 64
// weights in registers. Per step: 64 FFMA + shfl pair-reduce; 64 gate lanes
// compute c/h exactly (expf/tanhf); new h (64 floats) pushed to peer CTA via
// st.shared::cluster; one cluster barrier per step. h double-buffered.
// ---------------------------------------------------------------------------
__global__ void __launch_bounds__(512, 1) __cluster_dims__(2, 1, 1)
lstm_kernel(const float* __restrict__ xz,   // (8,256,512), bias already added
            const float* __restrict__ Wr,   // (128,512)
            float* __restrict__ out)        // full output buffer
{
  __shared__ __align__(16) float h_buf[2][128];
  __shared__ float z_sh[256];

  uint32_t rank; asm("mov.u32 %0, %%cluster_ctarank;" : "=r"(rank));
  const int b    = blockIdx.x >> 1;
  const int t    = threadIdx.x;
  const int c    = t >> 1;        // local column 0..255
  const int half = t & 1;         // K-half: rows [half*64, half*64+64)
  const int g    = c >> 6;        // gate 0..3 (i,f,g,o)
  const int mloc = c & 63;
  const int m    = (int)rank * 64 + mloc;   // global state index this CTA owns
  const int zcol = g * 128 + m;             // column in the 512-wide z

  // Register-resident recurrent weights for this thread's (column, K-half)
  float w[64];
  #pragma unroll
  for (int i = 0; i < 64; i++) w[i] = Wr[(size_t)(half*64 + i)*512 + zcol];

  if (t < 128) h_buf[0][t] = 0.f;
  float c_val = 0.f;   // cell state, lives in gate lanes (t<64)
  __syncthreads();
  asm volatile("barrier.cluster.arrive.aligned;" ::: "memory");
  asm volatile("barrier.cluster.wait.aligned;"  ::: "memory");

  const float* xz_b  = xz  + (size_t)b * 256 * 512;
  float*       out_b = out + (size_t)b * 256 * 256;
  float xz_next = (half == 0) ? xz_b[zcol] : 0.f;   // prefetch step 0

  // Peer CTA's h_buf base (distributed shared memory)
  uint32_t peer_h;
  {
    uint32_t laddr = smem_u32(&h_buf[0][0]);
    asm("mapa.shared::cluster.u32 %0, %1, %2;" : "=r"(peer_h) : "r"(laddr), "r"(rank ^ 1u));
  }

  for (int step = 0; step < 256; step++){
    const int s = step & 1;

    // partial dot: sum over this thread's 64 K-rows (weights in regs, h broadcast)
    float acc = 0.f;
    const float4* hv = (const float4*)&h_buf[s][half * 64];
    #pragma unroll
    for (int i4 = 0; i4 < 16; i4++){
      float4 h4 = hv[i4];
      acc = fmaf(h4.x, w[i4*4+0], acc);
      acc = fmaf(h4.y, w[i4*4+1], acc);
      acc = fmaf(h4.z, w[i4*4+2], acc);
      acc = fmaf(h4.w, w[i4*4+3], acc);
    }
    // combine the two K-halves (lanes t, t^1 are in the same warp)
    acc += __shfl_xor_sync(0xffffffffu, acc, 1);
    if (half == 0) z_sh[c] = acc + xz_next;
    if (half == 0 && step + 1 < 256)
      xz_next = xz_b[(size_t)(step + 1)*512 + zcol];
    __syncthreads();

    if (t < 64){
      float zi = z_sh[t];
      float zf = z_sh[64  + t];
      float zg = z_sh[128 + t];
      float zo = z_sh[192 + t];
      float ig = 1.f / (1.f + expf(-zi));
      float fg = 1.f / (1.f + expf(-zf));
      float gv = tanhf(zg);
      float og = 1.f / (1.f + expf(-zo));
      c_val = fg * c_val + ig * gv;
      float hn = og * tanhf(c_val);

      const int s2   = (step + 1) & 1;
      const int midx = (int)rank * 64 + t;
      h_buf[s2][midx] = hn;
      uint32_t raddr = peer_h + (uint32_t)(s2*128 + midx)*4u;
      asm volatile("st.shared::cluster.f32 [%0], %1;" :: "r"(raddr), "f"(hn) : "memory");

      out_b[(size_t)step*256 + midx] = hn;       // x goes to out[..., 0:128]
      if (step == 255){
        out[H_OFF + b*128 + midx] = hn;
        out[C_OFF + b*128 + midx] = c_val;
      }
    }
    // cluster barrier: release own writes (incl. remote st), acquire peer's
    asm volatile("barrier.cluster.arrive.aligned;" ::: "memory");
    asm volatile("barrier.cluster.wait.aligned;"  ::: "memory");
  }
}

// ---------------------------------------------------------------------------
// Bahdanau attention, flash-style. Block = (batch b, 8 query rows).
// Pass 1: stream 32-key chunks, scores[i][k] = sum_l tanh(keys[k][l]+q[i][l])*W3[l]
//   using MUFU tanh.approx. Full 8x512 score rows kept in smem.
// Softmax per row (one warp per row), then Pass 2: weighted sum over attended,
// reusing the key smem buffer (stride 132 — conflict-free LDS.128).
// Writes out[..., 128:256].
// ---------------------------------------------------------------------------
__global__ void __launch_bounds__(256) attn_kernel(
    const float* __restrict__ q,     // (8,256,128)
    const float* __restrict__ keys,  // (8,512,128)
    const float* __restrict__ att,   // (8,512,128) attended_inputs
    const float* __restrict__ W3,    // (128)
    float* __restrict__ out)
{
  __shared__ __align__(16) float q_sm[8*128];
  __shared__ __align__(16) float ksm[32*132];
  __shared__ float s_sm[8*512];
  __shared__ __align__(16) float w3_sm[128];
  __shared__ float rowinv[8];

  const int tid = threadIdx.x;
  const int b   = blockIdx.y;
  const int q0  = blockIdx.x * 8;

  // stage q tile (8 rows x 128) and W3
  ((float4*)q_sm)[tid] = ((const float4*)(q + ((size_t)(b*256 + q0))*128))[tid];
  if (tid < 128) w3_sm[tid] = W3[tid];

  const int i = tid >> 5;   // query row 0..7
  const int k = tid & 31;   // key-in-chunk 0..31

  // ----- pass 1: scores -----
  for (int kc = 0; kc < 16; kc++){
    __syncthreads();
    const float4* src = (const float4*)(keys + ((size_t)b*512 + kc*32)*128);
    for (int idx = tid; idx < 1024; idx += 256){
      int kk = idx >> 5, l4 = idx & 31;
      *(float4*)&ksm[kk*132 + l4*4] = src[idx];
    }
    __syncthreads();

    const float4* qv = (const float4*)&q_sm[i*128];
    const float4* kv = (const float4*)&ksm[k*132];
    const float4* wv = (const float4*)w3_sm;
    float acc = 0.f;
    #pragma unroll
    for (int l4 = 0; l4 < 32; l4++){
      float4 q4 = qv[l4], k4 = kv[l4], w4 = wv[l4];
      acc = fmaf(tanh_fast(q4.x + k4.x), w4.x, acc);
      acc = fmaf(tanh_fast(q4.y + k4.y), w4.y, acc);
      acc = fmaf(tanh_fast(q4.z + k4.z), w4.z, acc);
      acc = fmaf(tanh_fast(q4.w + k4.w), w4.w, acc);
    }
    s_sm[i*512 + kc*32 + k] = acc;   // b3 is a constant shift — softmax-invariant
  }
  __syncthreads();

  // ----- softmax: warp w handles row w -----
  {
    const int wrp = tid >> 5, lane = tid & 31;
    float mx = -1e30f;
    for (int jj = lane; jj < 512; jj += 32) mx = fmaxf(mx, s_sm[wrp*512 + jj]);
    #pragma unroll
    for (int o = 16; o > 0; o >>= 1) mx = fmaxf(mx, __shfl_xor_sync(~0u, mx, o));
    float sum = 0.f;
    for (int jj = lane; jj < 512; jj += 32){
      float e = __expf(s_sm[wrp*512 + jj] - mx);
      s_sm[wrp*512 + jj] = e;
      sum += e;
    }
    #pragma unroll
    for (int o = 16; o > 0; o >>= 1) sum += __shfl_xor_sync(~0u, sum, o);
    if (lane == 0) rowinv[wrp] = 1.f / sum;
  }

  // ----- pass 2: weighted = attn @ attended -----
  const int d  = tid & 127;   // output feature
  const int ih = tid >> 7;    // row group (rows ih*4 .. ih*4+3)
  float acc2[4] = {0.f, 0.f, 0.f, 0.f};
  for (int kc = 0; kc < 16; kc++){
    __syncthreads();
    const float4* src = (const float4*)(att + ((size_t)b*512 + kc*32)*128);
    for (int idx = tid; idx < 1024; idx += 256){
      int kk = idx >> 5, l4 = idx & 31;
      *(float4*)&ksm[kk*132 + l4*4] = src[idx];
    }
    __syncthreads();
    #pragma unroll 4
    for (int kk = 0; kk < 32; kk++){
      float a = ksm[kk*132 + d];
      #pragma unroll
      for (int ii = 0; ii < 4; ii++)
        acc2[ii] = fmaf(s_sm[(ih*4 + ii)*512 + kc*32 + kk], a, acc2[ii]);
    }
  }
  #pragma unroll
  for (int ii = 0; ii < 4; ii++){
    int row = ih*4 + ii;
    out[((size_t)(b*256) + q0 + row)*256 + 128 + d] = acc2[ii] * rowinv[row];
  }
}

// ---------------------------------------------------------------------------
extern "C" void kernel_launch(void* const* d_in, const int* in_sizes, int n_in,
                              void* d_out, int out_size)
{
  const float* inputs   = (const float*)d_in[0];   // (8,256,128)
  const float* attended = (const float*)d_in[1];   // (8,512,128)
  const float* Wk       = (const float*)d_in[2];   // (128,512)
  const float* Wr       = (const float*)d_in[3];   // (128,512)
  const float* bl       = (const float*)d_in[4];   // (512)
  const float* W1       = (const float*)d_in[5];   // (128,128)
  const float* b1       = (const float*)d_in[6];   // (128)
  const float* W2       = (const float*)d_in[7];   // (128,128)
  const float* b2       = (const float*)d_in[8];   // (128)
  const float* W3       = (const float*)d_in[9];   // (128,1)
  float* out = (float*)d_out;

  float *xz, *keys, *q;
  cudaGetSymbolAddress((void**)&xz,   g_xz);
  cudaGetSymbolAddress((void**)&keys, g_keys);
  cudaGetSymbolAddress((void**)&q,    g_q);

  // xz = inputs @ lstm_kernel + bias   (2048 x 512, K=128)
  gemm16_kernel<<<128, 512>>>(inputs, 128, Wk, bl, xz, 512, 512);
  // keys = attended @ W1 + b1          (4096 x 128, K=128)
  gemm16_kernel<<<256, 128>>>(attended, 128, W1, b1, keys, 128, 128);
  // LSTM scan — writes x into out[...,0:128] and h/c tails
  lstm_kernel<<<16, 512>>>(xz, Wr, out);
  // q = x @ W2 + b2                    (2048 x 128, K=128); x read from out (ld=256)
  gemm16_kernel<<<128, 128>>>(out, 256, W2, b2, q, 128, 128);
  // attention — writes out[...,128:256]
  attn_kernel<<<dim3(32, 8), 256>>>(q, keys, attended, W3, out);
}

// round 8
// speedup vs baseline: 1.4117x; 1.4117x over previous
#include <cuda_runtime.h>
#include <cstdint>
#include <math.h>

// Problem: B=8, T_OUT=256, T_IN=512, L=128, D_IN=128, D_ATT=128
// out = concat(x, weighted) (8,256,256) then h (8,128) then c (8,128)
#define H_OFF (8*256*256)
#define C_OFF (H_OFF + 8*128)

// Scratch (device globals — no allocation allowed)
__device__ float g_xz[8*256*512];     // input projection + bias
__device__ float g_keys[8*512*128];   // attended @ W1 + b1
__device__ float g_q[8*256*128];      // x @ W2 + b2

__device__ __forceinline__ uint32_t smem_u32(const void* p){
  uint32_t a;
  asm("{ .reg .u64 t; cvta.to.shared.u64 t, %1; cvt.u32.u64 %0, t; }" : "=r"(a) : "l"(p));
  return a;
}
__device__ __forceinline__ float tanh_fast(float x){
  float y; asm("tanh.approx.f32 %0, %1;" : "=f"(y) : "f"(x)); return y;
}
// Accurate-enough fast transcendentals (MUFU ex2 + rcp, ~1e-7 rel err)
__device__ __forceinline__ float sig_f(float x){
  return __fdividef(1.f, 1.f + __expf(-x));
}
__device__ __forceinline__ float tanh_e(float x){
  return 1.f - __fdividef(2.f, __expf(2.f*x) + 1.f);
}
__device__ __forceinline__ void mbar_wait_cluster(uint32_t addr, uint32_t parity){
  asm volatile(
    "{\n\t"
    ".reg .pred P1;\n\t"
    "WAIT_LOOP_%=:\n\t"
    "mbarrier.try_wait.parity.acquire.cluster.shared::cta.b64 P1, [%0], %1, 0x989680;\n\t"
    "@P1 bra.uni WAIT_DONE_%=;\n\t"
    "bra.uni WAIT_LOOP_%=;\n\t"
    "WAIT_DONE_%=:\n\t"
    "}"
    :: "r"(addr), "r"(parity) : "memory");
}

// ---------------------------------------------------------------------------
// GEMM: C[M,N] = A[M,128] @ B[128,N] + bias[N].
// Block = 16 rows x 128 cols. grid = (M/16, N/128). blockDim = 128.
// B slice staged in smem in two 64-row stages (batched loads -> high MLP,
// then the inner loop is pure LDS + FFMA).
// ---------------------------------------------------------------------------
__global__ void __launch_bounds__(128) gemm16s_kernel(
    const float* __restrict__ A, int lda,
    const float* __restrict__ Bm, const float* __restrict__ bias,
    float* __restrict__ C, int ldc, int N)
{
  __shared__ __align__(16) float asT[128*16];  // A tile, transposed
  __shared__ float bs[64*128];                 // B stage (64 rows x 128 cols)
  const int j  = threadIdx.x;                  // local col 0..127
  const int jc = blockIdx.y*128 + j;           // global col
  const int r0 = blockIdx.x*16;

  // A tile: thread j loads column j of 16 rows (coalesced per row)
  #pragma unroll
  for (int r = 0; r < 16; r++)
    asT[j*16 + r] = A[(size_t)(r0 + r)*lda + j];

  float bv = bias[jc];
  float acc[16];
  #pragma unroll
  for (int r = 0; r < 16; r++) acc[r] = bv;

  for (int kb = 0; kb < 2; kb++){
    __syncthreads();
    #pragma unroll 16
    for (int l = 0; l < 64; l++)
      bs[l*128 + j] = Bm[(size_t)(kb*64 + l)*N + jc];
    __syncthreads();
    #pragma unroll 8
    for (int l = 0; l < 64; l++){
      float wv = bs[l*128 + j];
      const float4* ap = (const float4*)&asT[(kb*64 + l)*16];
      float4 a0 = ap[0], a1 = ap[1], a2 = ap[2], a3 = ap[3];
      acc[0]  = fmaf(a0.x, wv, acc[0]);  acc[1]  = fmaf(a0.y, wv, acc[1]);
      acc[2]  = fmaf(a0.z, wv, acc[2]);  acc[3]  = fmaf(a0.w, wv, acc[3]);
      acc[4]  = fmaf(a1.x, wv, acc[4]);  acc[5]  = fmaf(a1.y, wv, acc[5]);
      acc[6]  = fmaf(a1.z, wv, acc[6]);  acc[7]  = fmaf(a1.w, wv, acc[7]);
      acc[8]  = fmaf(a2.x, wv, acc[8]);  acc[9]  = fmaf(a2.y, wv, acc[9]);
      acc[10] = fmaf(a2.z, wv, acc[10]); acc[11] = fmaf(a2.w, wv, acc[11]);
      acc[12] = fmaf(a3.x, wv, acc[12]); acc[13] = fmaf(a3.y, wv, acc[13]);
      acc[14] = fmaf(a3.z, wv, acc[14]); acc[15] = fmaf(a3.w, wv, acc[15]);
    }
  }

  #pragma unroll
  for (int r = 0; r < 16; r++) C[(size_t)(r0 + r)*ldc + jc] = acc[r];
}

// ---------------------------------------------------------------------------
// LSTM scan. Cluster of 2 CTAs per batch; grid = 16 CTAs. CTA rank r owns
// state rows [64r, 64r+64). Recurrent weights register-resident (64/thread).
// Per step: 64 FFMA + shfl pair-reduce, fast gates (__expf-based), new h
// pushed to peer via st.shared::cluster, then a ping-pong mbarrier handshake
// (mbar[step&1], 64 release-arrives from the peer's gate lanes per phase)
// replaces barrier.cluster. Two alternating barriers make cross-step arrival
// mixing causally impossible.
// ---------------------------------------------------------------------------
__global__ void __launch_bounds__(512, 1) __cluster_dims__(2, 1, 1)
lstm_kernel(const float* __restrict__ xz,   // (8,256,512), bias already added
            const float* __restrict__ Wr,   // (128,512)
            float* __restrict__ out)        // full output buffer
{
  __shared__ __align__(16) float h_buf[2][128];
  __shared__ float z_sh[256];
  __shared__ __align__(8) uint64_t mbar[2];

  uint32_t rank; asm("mov.u32 %0, %%cluster_ctarank;" : "=r"(rank));
  const int b    = blockIdx.x >> 1;
  const int t    = threadIdx.x;
  const int c    = t >> 1;        // local column 0..255
  const int half = t & 1;         // K-half: rows [half*64, half*64+64)
  const int g    = c >> 6;        // gate 0..3 (i,f,g,o)
  const int mloc = c & 63;
  const int m    = (int)rank * 64 + mloc;
  const int zcol = g * 128 + m;

  float w[64];
  #pragma unroll
  for (int i = 0; i < 64; i++) w[i] = Wr[(size_t)(half*64 + i)*512 + zcol];

  uint32_t mbar_l = smem_u32(&mbar[0]);
  if (t == 0){
    asm volatile("mbarrier.init.shared.b64 [%0], %1;" :: "r"(mbar_l),      "r"(64u) : "memory");
    asm volatile("mbarrier.init.shared.b64 [%0], %1;" :: "r"(mbar_l + 8u), "r"(64u) : "memory");
  }
  if (t < 128) h_buf[0][t] = 0.f;
  float c_val = 0.f;
  __syncthreads();
  // peer must see our mbarrier init before it can remote-arrive
  asm volatile("barrier.cluster.arrive.aligned;" ::: "memory");
  asm volatile("barrier.cluster.wait.aligned;"  ::: "memory");

  uint32_t peer_h, peer_mb;
  {
    uint32_t lh = smem_u32(&h_buf[0][0]);
    asm("mapa.shared::cluster.u32 %0, %1, %2;" : "=r"(peer_h)  : "r"(lh),     "r"(rank ^ 1u));
    asm("mapa.shared::cluster.u32 %0, %1, %2;" : "=r"(peer_mb) : "r"(mbar_l), "r"(rank ^ 1u));
  }

  const float* xz_b  = xz  + (size_t)b * 256 * 512;
  float*       out_b = out + (size_t)b * 256 * 256;
  float xz_next = (half == 0) ? xz_b[zcol] : 0.f;   // prefetch step 0

  for (int step = 0; step < 256; step++){
    const int s = step & 1;

    float acc = 0.f;
    const float4* hv = (const float4*)&h_buf[s][half * 64];
    #pragma unroll
    for (int i4 = 0; i4 < 16; i4++){
      float4 h4 = hv[i4];
      acc = fmaf(h4.x, w[i4*4+0], acc);
      acc = fmaf(h4.y, w[i4*4+1], acc);
      acc = fmaf(h4.z, w[i4*4+2], acc);
      acc = fmaf(h4.w, w[i4*4+3], acc);
    }
    acc += __shfl_xor_sync(0xffffffffu, acc, 1);
    if (half == 0){
      z_sh[c] = acc + xz_next;
      if (step + 1 < 256) xz_next = xz_b[(size_t)(step + 1)*512 + zcol];
    }
    __syncthreads();

    if (t < 64){
      float zi = z_sh[t];
      float zf = z_sh[64  + t];
      float zg = z_sh[128 + t];
      float zo = z_sh[192 + t];
      float ig = sig_f(zi);
      float fg = sig_f(zf);
      float gv = tanh_e(zg);
      float og = sig_f(zo);
      c_val = fg * c_val + ig * gv;
      float hn = og * tanh_e(c_val);

      const int s2   = (step + 1) & 1;
      const int midx = (int)rank * 64 + t;
      h_buf[s2][midx] = hn;
      asm volatile("st.shared::cluster.f32 [%0], %1;"
        :: "r"(peer_h + (uint32_t)(s2*128 + midx)*4u), "f"(hn) : "memory");

      out_b[(size_t)step*256 + midx] = hn;
      if (step == 255){
        out[H_OFF + b*128 + midx] = hn;
        out[C_OFF + b*128 + midx] = c_val;
      }
      // release-arrive on peer's barrier for THIS step (orders the store above)
      asm volatile("mbarrier.arrive.shared::cluster.b64 _, [%0];"
        :: "r"(peer_mb + (uint32_t)s*8u) : "memory");
    }
    __syncthreads();
    // wait for peer's 64 arrivals on our mbar[s]; phase parity = (step>>1)&1
    mbar_wait_cluster(mbar_l + (uint32_t)s*8u, (uint32_t)((step >> 1) & 1));
  }
  asm volatile("barrier.cluster.arrive.aligned;" ::: "memory");
  asm volatile("barrier.cluster.wait.aligned;"  ::: "memory");
}

// ---------------------------------------------------------------------------
// Bahdanau attention, flash-style (unchanged from R4 — ~10% of runtime).
// ---------------------------------------------------------------------------
__global__ void __launch_bounds__(256) attn_kernel(
    const float* __restrict__ q,     // (8,256,128)
    const float* __restrict__ keys,  // (8,512,128)
    const float* __restrict__ att,   // (8,512,128)
    const float* __restrict__ W3,    // (128)
    float* __restrict__ out)
{
  __shared__ __align__(16) float q_sm[8*128];
  __shared__ __align__(16) float ksm[32*132];
  __shared__ float s_sm[8*512];
  __shared__ __align__(16) float w3_sm[128];
  __shared__ float rowinv[8];

  const int tid = threadIdx.x;
  const int b   = blockIdx.y;
  const int q0  = blockIdx.x * 8;

  ((float4*)q_sm)[tid] = ((const float4*)(q + ((size_t)(b*256 + q0))*128))[tid];
  if (tid < 128) w3_sm[tid] = W3[tid];

  const int i = tid >> 5;   // query row 0..7
  const int k = tid & 31;   // key-in-chunk 0..31

  for (int kc = 0; kc < 16; kc++){
    __syncthreads();
    const float4* src = (const float4*)(keys + ((size_t)b*512 + kc*32)*128);
    for (int idx = tid; idx < 1024; idx += 256){
      int kk = idx >> 5, l4 = idx & 31;
      *(float4*)&ksm[kk*132 + l4*4] = src[idx];
    }
    __syncthreads();

    const float4* qv = (const float4*)&q_sm[i*128];
    const float4* kv = (const float4*)&ksm[k*132];
    const float4* wv = (const float4*)w3_sm;
    float acc = 0.f;
    #pragma unroll
    for (int l4 = 0; l4 < 32; l4++){
      float4 q4 = qv[l4], k4 = kv[l4], w4 = wv[l4];
      acc = fmaf(tanh_fast(q4.x + k4.x), w4.x, acc);
      acc = fmaf(tanh_fast(q4.y + k4.y), w4.y, acc);
      acc = fmaf(tanh_fast(q4.z + k4.z), w4.z, acc);
      acc = fmaf(tanh_fast(q4.w + k4.w), w4.w, acc);
    }
    s_sm[i*512 + kc*32 + k] = acc;
  }
  __syncthreads();

  {
    const int wrp = tid >> 5, lane = tid & 31;
    float mx = -1e30f;
    for (int jj = lane; jj < 512; jj += 32) mx = fmaxf(mx, s_sm[wrp*512 + jj]);
    #pragma unroll
    for (int o = 16; o > 0; o >>= 1) mx = fmaxf(mx, __shfl_xor_sync(~0u, mx, o));
    float sum = 0.f;
    for (int jj = lane; jj < 512; jj += 32){
      float e = __expf(s_sm[wrp*512 + jj] - mx);
      s_sm[wrp*512 + jj] = e;
      sum += e;
    }
    #pragma unroll
    for (int o = 16; o > 0; o >>= 1) sum += __shfl_xor_sync(~0u, sum, o);
    if (lane == 0) rowinv[wrp] = 1.f / sum;
  }

  const int d  = tid & 127;
  const int ih = tid >> 7;
  float acc2[4] = {0.f, 0.f, 0.f, 0.f};
  for (int kc = 0; kc < 16; kc++){
    __syncthreads();
    const float4* src = (const float4*)(att + ((size_t)b*512 + kc*32)*128);
    for (int idx = tid; idx < 1024; idx += 256){
      int kk = idx >> 5, l4 = idx & 31;
      *(float4*)&ksm[kk*132 + l4*4] = src[idx];
    }
    __syncthreads();
    #pragma unroll 4
    for (int kk = 0; kk < 32; kk++){
      float a = ksm[kk*132 + d];
      #pragma unroll
      for (int ii = 0; ii < 4; ii++)
        acc2[ii] = fmaf(s_sm[(ih*4 + ii)*512 + kc*32 + kk], a, acc2[ii]);
    }
  }
  #pragma unroll
  for (int ii = 0; ii < 4; ii++){
    int row = ih*4 + ii;
    out[((size_t)(b*256) + q0 + row)*256 + 128 + d] = acc2[ii] * rowinv[row];
  }
}

// ---------------------------------------------------------------------------
extern "C" void kernel_launch(void* const* d_in, const int* in_sizes, int n_in,
                              void* d_out, int out_size)
{
  const float* inputs   = (const float*)d_in[0];   // (8,256,128)
  const float* attended = (const float*)d_in[1];   // (8,512,128)
  const float* Wk       = (const float*)d_in[2];   // (128,512)
  const float* Wr       = (const float*)d_in[3];   // (128,512)
  const float* bl       = (const float*)d_in[4];   // (512)
  const float* W1       = (const float*)d_in[5];   // (128,128)
  const float* b1       = (const float*)d_in[6];   // (128)
  const float* W2       = (const float*)d_in[7];   // (128,128)
  const float* b2       = (const float*)d_in[8];   // (128)
  const float* W3       = (const float*)d_in[9];   // (128,1)
  float* out = (float*)d_out;

  float *xz, *keys, *q;
  cudaGetSymbolAddress((void**)&xz,   g_xz);
  cudaGetSymbolAddress((void**)&keys, g_keys);
  cudaGetSymbolAddress((void**)&q,    g_q);

  // xz = inputs @ lstm_kernel + bias   (2048 x 512, K=128)
  gemm16s_kernel<<<dim3(128, 4), 128>>>(inputs, 128, Wk, bl, xz, 512, 512);
  // keys = attended @ W1 + b1          (4096 x 128, K=128)
  gemm16s_kernel<<<dim3(256, 1), 128>>>(attended, 128, W1, b1, keys, 128, 128);
  // LSTM scan — writes x into out[...,0:128] and h/c tails
  lstm_kernel<<<16, 512>>>(xz, Wr, out);
  // q = x @ W2 + b2                    (2048 x 128, K=128); x read from out (ld=256)
  gemm16s_kernel<<<dim3(128, 1), 128>>>(out, 256, W2, b2, q, 128, 128);
  // attention — writes out[...,128:256]
  attn_kernel<<<dim3(32, 8), 256>>>(q, keys, attended, W3, out);
}